// round 13
// baseline (speedup 1.0000x reference)
#include <cuda_runtime.h>

#define MARGIN  1.9f
#define GRID    592              // 4 blocks/SM on 148 SMs, all wave-1 resident
#define NMAXE   1024
#define BIGF    3.0e38f
#define BSCALE  8.0f             // 256 buckets over t in [0,32)

// Scratch (no allocation allowed)
__device__ float g_dot[640 * 640];   // full dot products (mirror filled from upper tiles)
__device__ float g_sq[NMAXE];        // = diag(dot), written by diagonal tiles
__device__ int   g_lab[NMAXE];
__device__ float g_bsum[GRID];
__device__ int   g_bcnt[GRID];
__device__ int   g_bval2[GRID];
__device__ int   g_bar1 = 0;
__device__ int   g_bar2 = 0;

// Fused kernel, grid=592:
//  phase 1: blocks 0..209 : UPPER-TRIANGLE 32x32 dot tiles (mirror via smem
//                           transpose; diag tiles emit g_sq). block 210: labels.
//  grid barrier
//  phase 2: block b -> anchors i = b, b+592. POSITIVE-side counting sort
//           (~64 elems): histogram positives' thresholds t=d_p+M, prefix
//           scans, then each of ~576 negatives answers via O(1) suffix
//           lookup + exact boundary-bucket scan. No P x N loop.
//  phase 3: last block reduces partials -> out[4], resets barriers
__global__ void __launch_bounds__(256, 4)
fused_triplet_kernel(const float* __restrict__ e, const int* __restrict__ lab32,
                     float* __restrict__ out, int n) {
    __shared__ float As[32 * 132];   // A tile, 16.9 KB (phase 1)
    __shared__ float Bs[128 * 32];   // B tile k-major, 16 KB (also transpose buf)
    // phase 2 histogram structures (positives side, ~64 elements)
    __shared__ int   hcnt[256];
    __shared__ int   pcs[257];       // exclusive prefix of counts; pcs[256]=P
    __shared__ int   cur[256];       // scatter cursors
    __shared__ float pvs[257];       // exclusive prefix of bucket sums; pvs[256]=tot
    __shared__ float bval[704];      // positives' t values grouped by bucket
    __shared__ int   swi[8], swi2[8];
    __shared__ float swf[8], swf2[8];
    __shared__ int   s_old, s_is64;
    __shared__ float wsum[8];
    __shared__ int   wcnt[8];

    const int b    = blockIdx.x;
    const int tid  = threadIdx.x;
    const int lane = tid & 31;
    const int wid  = tid >> 5;
    const float4* e4 = (const float4*)e;   // 32 float4 per embedding row

    const int tiles_x    = n >> 5;                        // 20
    const int tri_blocks = (tiles_x * (tiles_x + 1)) / 2; // 210
    const int lab_block  = tri_blocks;                    // 210

    // ================= phase 1 =================
    if (b < tri_blocks) {
        int ti = 0, rrem = b;
        #pragma unroll 1
        for (; ti < tiles_x; ti++) {
            int cnt = tiles_x - ti;
            if (rrem < cnt) break;
            rrem -= cnt;
        }
        const int tj = ti + rrem;

        const int tx = tid & 15;
        const int ty = tid >> 4;

        #pragma unroll
        for (int r = 0; r < 4; r++) {
            int lin = tid + r * 256;
            int row = lin >> 5;
            int c4  = lin & 31;
            float4 v = e4[(size_t)(ti * 32 + row) * 32 + c4];
            *(float4*)&As[row * 132 + c4 * 4] = v;
        }
        #pragma unroll
        for (int r = 0; r < 4; r++) {
            int lin = tid + r * 256;
            int j   = lin & 31;
            int c4  = lin >> 5;
            float4 v = e4[(size_t)(tj * 32 + j) * 32 + c4];
            Bs[(c4 * 4 + 0) * 32 + j] = v.x;
            Bs[(c4 * 4 + 1) * 32 + j] = v.y;
            Bs[(c4 * 4 + 2) * 32 + j] = v.z;
            Bs[(c4 * 4 + 3) * 32 + j] = v.w;
        }
        __syncthreads();

        float acc00 = 0.f, acc01 = 0.f, acc10 = 0.f, acc11 = 0.f;
        #pragma unroll 4
        for (int k4 = 0; k4 < 32; k4++) {
            float4 a0 = *(const float4*)&As[(2 * ty + 0) * 132 + 4 * k4];
            float4 a1 = *(const float4*)&As[(2 * ty + 1) * 132 + 4 * k4];
            float2 b0 = *(const float2*)&Bs[(4 * k4 + 0) * 32 + 2 * tx];
            float2 b1 = *(const float2*)&Bs[(4 * k4 + 1) * 32 + 2 * tx];
            float2 b2 = *(const float2*)&Bs[(4 * k4 + 2) * 32 + 2 * tx];
            float2 b3 = *(const float2*)&Bs[(4 * k4 + 3) * 32 + 2 * tx];
            acc00 = fmaf(a0.x, b0.x, acc00);
            acc01 = fmaf(a0.x, b0.y, acc01);
            acc10 = fmaf(a1.x, b0.x, acc10);
            acc11 = fmaf(a1.x, b0.y, acc11);
            acc00 = fmaf(a0.y, b1.x, acc00);
            acc01 = fmaf(a0.y, b1.y, acc01);
            acc10 = fmaf(a1.y, b1.x, acc10);
            acc11 = fmaf(a1.y, b1.y, acc11);
            acc00 = fmaf(a0.z, b2.x, acc00);
            acc01 = fmaf(a0.z, b2.y, acc01);
            acc10 = fmaf(a1.z, b2.x, acc10);
            acc11 = fmaf(a1.z, b2.y, acc11);
            acc00 = fmaf(a0.w, b3.x, acc00);
            acc01 = fmaf(a0.w, b3.y, acc01);
            acc10 = fmaf(a1.w, b3.x, acc10);
            acc11 = fmaf(a1.w, b3.y, acc11);
        }
        const int row0 = ti * 32 + 2 * ty;
        const int col0 = tj * 32 + 2 * tx;
        *(float2*)&g_dot[(size_t)(row0 + 0) * n + col0] = make_float2(acc00, acc01);
        *(float2*)&g_dot[(size_t)(row0 + 1) * n + col0] = make_float2(acc10, acc11);

        if (ti == tj) {
            if (2 * ty     == 2 * tx    ) g_sq[row0]     = acc00;
            if (2 * ty     == 2 * tx + 1) g_sq[row0]     = acc01;
            if (2 * ty + 1 == 2 * tx    ) g_sq[row0 + 1] = acc10;
            if (2 * ty + 1 == 2 * tx + 1) g_sq[row0 + 1] = acc11;
        } else {
            float* Tr = Bs;                  // reuse: [32][33]
            __syncthreads();
            Tr[(2 * tx + 0) * 33 + 2 * ty + 0] = acc00;
            Tr[(2 * tx + 1) * 33 + 2 * ty + 0] = acc01;
            Tr[(2 * tx + 0) * 33 + 2 * ty + 1] = acc10;
            Tr[(2 * tx + 1) * 33 + 2 * ty + 1] = acc11;
            __syncthreads();
            int trow = tid >> 3;
            int tc4  = tid & 7;
            float4 mv;
            mv.x = Tr[trow * 33 + tc4 * 4 + 0];
            mv.y = Tr[trow * 33 + tc4 * 4 + 1];
            mv.z = Tr[trow * 33 + tc4 * 4 + 2];
            mv.w = Tr[trow * 33 + tc4 * 4 + 3];
            *(float4*)&g_dot[(size_t)(tj * 32 + trow) * n + ti * 32 + tc4 * 4] = mv;
        }
    } else if (b == lab_block) {
        if (tid == 0) s_is64 = 1;
        __syncthreads();
        for (int idx = tid; idx < n / 2; idx += 256)
            if (lab32[2 * idx + 1] != 0) atomicExch(&s_is64, 0);
        __syncthreads();
        const bool is64 = (s_is64 != 0);
        for (int i2 = tid; i2 < n; i2 += 256)
            g_lab[i2] = is64 ? lab32[2 * i2] : lab32[i2];
    }

    // ================= grid barrier =================
    __threadfence();
    __syncthreads();
    if (tid == 0) {
        atomicAdd(&g_bar1, 1);
        volatile int* vb = &g_bar1;
        while (*vb < GRID) { __nanosleep(32); }
    }
    __syncthreads();

    // ================= phase 2: positive-side counting sort =================
    float lsum = 0.f;
    int   lcnt = 0;
    int   vtot = 0;

    for (int i = b; i < n; i += GRID) {
        const int   li  = g_lab[i];
        const float sqi = g_sq[i];
        const float* __restrict__ drow = &g_dot[(size_t)i * n];

        __syncthreads();                 // prev anchor's structures fully consumed
        hcnt[tid] = 0;
        __syncthreads();

        // classify j slots: negatives kept in regs (BIGF sentinel for same/self),
        // positives' thresholds t = d + M histogrammed.
        float nk0 = BIGF, nk1 = BIGF, nk2 = BIGF;
        float pv0 = 0.f, pv1 = 0.f, pv2 = 0.f;
        bool  ip0 = false, ip1 = false, ip2 = false;
        {
            int j = tid;
            float dv = sqrtf(fmaxf(sqi + g_sq[j] - 2.0f * drow[j], 0.0f));
            bool same = (g_lab[j] == li);
            nk0 = same ? BIGF : dv;
            ip0 = same && (j != i);
            pv0 = dv + MARGIN;
            if (ip0) atomicAdd(&hcnt[min(255, (int)(pv0 * BSCALE))], 1);
        }
        {
            int j = tid + 256;
            float dv = sqrtf(fmaxf(sqi + g_sq[j] - 2.0f * drow[j], 0.0f));
            bool same = (g_lab[j] == li);
            nk1 = same ? BIGF : dv;
            ip1 = same && (j != i);
            pv1 = dv + MARGIN;
            if (ip1) atomicAdd(&hcnt[min(255, (int)(pv1 * BSCALE))], 1);
        }
        if (tid + 512 < n) {
            int j = tid + 512;
            float dv = sqrtf(fmaxf(sqi + g_sq[j] - 2.0f * drow[j], 0.0f));
            bool same = (g_lab[j] == li);
            nk2 = same ? BIGF : dv;
            ip2 = same && (j != i);
            pv2 = dv + MARGIN;
            if (ip2) atomicAdd(&hcnt[min(255, (int)(pv2 * BSCALE))], 1);
        }
        __syncthreads();

        // exclusive scan of counts -> pcs, cursors
        int vcnt = hcnt[tid];
        int inc = vcnt;
        #pragma unroll
        for (int off = 1; off < 32; off <<= 1) {
            int t = __shfl_up_sync(0xFFFFFFFFu, inc, off);
            if (lane >= off) inc += t;
        }
        if (lane == 31) swi[wid] = inc;
        __syncthreads();
        if (tid < 8) {
            int o = 0;
            for (int k = 0; k < tid; k++) o += swi[k];
            swi2[tid] = o;
        }
        __syncthreads();
        int exc = inc - vcnt + swi2[wid];
        pcs[tid] = exc;
        cur[tid] = exc;
        if (tid == 255) pcs[256] = exc + vcnt;
        __syncthreads();

        // scatter positives' thresholds grouped by bucket
        if (ip0) { int bb = min(255, (int)(pv0 * BSCALE)); bval[atomicAdd(&cur[bb], 1)] = pv0; }
        if (ip1) { int bb = min(255, (int)(pv1 * BSCALE)); bval[atomicAdd(&cur[bb], 1)] = pv1; }
        if (ip2) { int bb = min(255, (int)(pv2 * BSCALE)); bval[atomicAdd(&cur[bb], 1)] = pv2; }
        __syncthreads();

        // per-bucket sums -> exclusive scan pvs (pvs[256] = total sum)
        float sv = 0.f;
        {
            int s0 = pcs[tid], s1 = pcs[tid + 1];
            for (int k = s0; k < s1; k++) sv += bval[k];
        }
        float fin = sv;
        #pragma unroll
        for (int off = 1; off < 32; off <<= 1) {
            float t = __shfl_up_sync(0xFFFFFFFFu, fin, off);
            if (lane >= off) fin += t;
        }
        if (lane == 31) swf[wid] = fin;
        __syncthreads();
        if (tid < 8) {
            float o = 0.f;
            for (int k = 0; k < tid; k++) o += swf[k];
            swf2[tid] = o;
        }
        __syncthreads();
        pvs[tid] = fin - sv + swf2[wid];
        if (tid == 255) pvs[256] = fin + swf2[wid];
        __syncthreads();

        // negatives query: cnt/sum of thresholds t_p > d_n (strict).
        // BIGF sentinels yield exactly 0 contribution (cnt_le = P).
        const int   P    = pcs[256];
        const float tots = pvs[256];
        {
            int bb = min(255, (int)fminf(nk0 * BSCALE, 255.0f));
            int cl = pcs[bb];
            float sl = pvs[bb];
            int e1 = pcs[bb + 1];
            for (int k = pcs[bb]; k < e1; k++) {
                float v = bval[k];
                if (v <= nk0) { cl++; sl += v; }
            }
            int cg = P - cl;
            lcnt += cg;
            lsum += (tots - sl) - (float)cg * nk0;
        }
        {
            int bb = min(255, (int)fminf(nk1 * BSCALE, 255.0f));
            int cl = pcs[bb];
            float sl = pvs[bb];
            int e1 = pcs[bb + 1];
            for (int k = pcs[bb]; k < e1; k++) {
                float v = bval[k];
                if (v <= nk1) { cl++; sl += v; }
            }
            int cg = P - cl;
            lcnt += cg;
            lsum += (tots - sl) - (float)cg * nk1;
        }
        if (tid + 512 < n) {
            int bb = min(255, (int)fminf(nk2 * BSCALE, 255.0f));
            int cl = pcs[bb];
            float sl = pvs[bb];
            int e1 = pcs[bb + 1];
            for (int k = pcs[bb]; k < e1; k++) {
                float v = bval[k];
                if (v <= nk2) { cl++; sl += v; }
            }
            int cg = P - cl;
            lcnt += cg;
            lsum += (tots - sl) - (float)cg * nk2;
        }

        vtot += P * (n - 1 - P);
    }

    // block reduce
    #pragma unroll
    for (int off = 16; off; off >>= 1) {
        lsum += __shfl_down_sync(0xFFFFFFFFu, lsum, off);
        lcnt += __shfl_down_sync(0xFFFFFFFFu, lcnt, off);
    }
    if (lane == 0) { wsum[wid] = lsum; wcnt[wid] = lcnt; }
    __syncthreads();
    if (tid == 0) {
        float s = 0.f; int c = 0;
        #pragma unroll
        for (int w = 0; w < 8; w++) { s += wsum[w]; c += wcnt[w]; }
        g_bsum[b]  = s;
        g_bcnt[b]  = c;
        g_bval2[b] = vtot;
    }

    // ================= phase 3: last block finalizes =================
    __threadfence();
    __syncthreads();
    if (tid == 0) s_old = atomicAdd(&g_bar2, 1);
    __syncthreads();
    if (s_old == GRID - 1) {
        float s = 0.f; int c = 0, v = 0;
        for (int idx = tid; idx < GRID; idx += 256) {
            s += g_bsum[idx];
            c += g_bcnt[idx];
            v += g_bval2[idx];
        }
        #pragma unroll
        for (int off = 16; off; off >>= 1) {
            s += __shfl_down_sync(0xFFFFFFFFu, s, off);
            c += __shfl_down_sync(0xFFFFFFFFu, c, off);
            v += __shfl_down_sync(0xFFFFFFFFu, v, off);
        }
        __shared__ float fs[8];
        __shared__ int   fc[8], fv[8];
        if (lane == 0) { fs[wid] = s; fc[wid] = c; fv[wid] = v; }
        __syncthreads();
        if (tid == 0) {
            float total = 0.f; int cnt = 0, val = 0;
            #pragma unroll
            for (int w = 0; w < 8; w++) { total += fs[w]; cnt += fc[w]; val += fv[w]; }
            float num_non   = (float)cnt;
            float num_valid = (float)val;
            out[0] = (cnt > 0) ? total / fmaxf(num_non, 1.0f) : 0.0f;
            out[1] = num_valid;
            out[2] = num_non;
            out[3] = num_non / (num_valid + 1e-16f);
            g_bar1 = 0;
            g_bar2 = 0;
            __threadfence();
        }
    }
}

extern "C" void kernel_launch(void* const* d_in, const int* in_sizes, int n_in,
                              void* d_out, int out_size) {
    const float* e   = (const float*)d_in[0];   // embeddings [8,80,128] fp32
    const int*   lab = (const int*)d_in[1];     // labels (int64 or int32 view)
    int n = in_sizes[1];                        // 640

    fused_triplet_kernel<<<GRID, 256>>>(e, lab, (float*)d_out, n);
}

// round 16
// speedup vs baseline: 1.0244x; 1.0244x over previous
#include <cuda_runtime.h>

#define MARGIN  1.9f
#define NANCH   640
#define NMAXE   1024
#define BIGF    3.0e38f

// Scratch (no allocation allowed)
__device__ float g_dot[640 * 640];   // full dot products (mirror filled from upper tiles)
__device__ float g_sq[NMAXE];        // = diag(dot), written by diagonal tiles
__device__ int   g_lab[NMAXE];
__device__ float g_bsum[NANCH];
__device__ int   g_bcnt[NANCH];
__device__ int   g_bval[NANCH];
__device__ int   g_done = 0;         // kernel-B tail counter (reset by finalizer)

// ============================================================================
// Kernel A: grid = 211.  Blocks 0..209: upper-triangle 32x32 dot tiles
// (2x2 micro, full k=128; diag tiles emit g_sq; off-diag mirror via smem
// transpose).  Block 210: label normalization (int64/int32 autodetect).
// ============================================================================
__global__ void __launch_bounds__(256)
gemm_kernel(const float* __restrict__ e, const int* __restrict__ lab32, int n) {
    __shared__ float As[32 * 132];   // A tile rows x k (padded)
    __shared__ float Bs[128 * 32];   // B tile k-major (reused as transpose buf)
    __shared__ int   s_is64;

    const int b   = blockIdx.x;
    const int tid = threadIdx.x;
    const float4* e4 = (const float4*)e;   // 32 float4 per embedding row

    const int tiles_x    = n >> 5;                        // 20
    const int tri_blocks = (tiles_x * (tiles_x + 1)) / 2; // 210

    if (b < tri_blocks) {
        // invert triangular index -> (ti, tj), tj >= ti
        int ti = 0, rrem = b;
        #pragma unroll 1
        for (; ti < tiles_x; ti++) {
            int cnt = tiles_x - ti;
            if (rrem < cnt) break;
            rrem -= cnt;
        }
        const int tj = ti + rrem;

        const int tx = tid & 15;     // col pair (cols 2tx, 2tx+1)
        const int ty = tid >> 4;     // row pair (rows 2ty, 2ty+1)

        #pragma unroll
        for (int r = 0; r < 4; r++) {
            int lin = tid + r * 256;
            int row = lin >> 5;
            int c4  = lin & 31;
            float4 v = e4[(size_t)(ti * 32 + row) * 32 + c4];
            *(float4*)&As[row * 132 + c4 * 4] = v;
        }
        #pragma unroll
        for (int r = 0; r < 4; r++) {
            int lin = tid + r * 256;
            int j   = lin & 31;
            int c4  = lin >> 5;
            float4 v = e4[(size_t)(tj * 32 + j) * 32 + c4];
            Bs[(c4 * 4 + 0) * 32 + j] = v.x;
            Bs[(c4 * 4 + 1) * 32 + j] = v.y;
            Bs[(c4 * 4 + 2) * 32 + j] = v.z;
            Bs[(c4 * 4 + 3) * 32 + j] = v.w;
        }
        __syncthreads();

        float acc00 = 0.f, acc01 = 0.f, acc10 = 0.f, acc11 = 0.f;
        #pragma unroll 4
        for (int k4 = 0; k4 < 32; k4++) {
            float4 a0 = *(const float4*)&As[(2 * ty + 0) * 132 + 4 * k4];
            float4 a1 = *(const float4*)&As[(2 * ty + 1) * 132 + 4 * k4];
            float2 b0 = *(const float2*)&Bs[(4 * k4 + 0) * 32 + 2 * tx];
            float2 b1 = *(const float2*)&Bs[(4 * k4 + 1) * 32 + 2 * tx];
            float2 b2 = *(const float2*)&Bs[(4 * k4 + 2) * 32 + 2 * tx];
            float2 b3 = *(const float2*)&Bs[(4 * k4 + 3) * 32 + 2 * tx];
            acc00 = fmaf(a0.x, b0.x, acc00);
            acc01 = fmaf(a0.x, b0.y, acc01);
            acc10 = fmaf(a1.x, b0.x, acc10);
            acc11 = fmaf(a1.x, b0.y, acc11);
            acc00 = fmaf(a0.y, b1.x, acc00);
            acc01 = fmaf(a0.y, b1.y, acc01);
            acc10 = fmaf(a1.y, b1.x, acc10);
            acc11 = fmaf(a1.y, b1.y, acc11);
            acc00 = fmaf(a0.z, b2.x, acc00);
            acc01 = fmaf(a0.z, b2.y, acc01);
            acc10 = fmaf(a1.z, b2.x, acc10);
            acc11 = fmaf(a1.z, b2.y, acc11);
            acc00 = fmaf(a0.w, b3.x, acc00);
            acc01 = fmaf(a0.w, b3.y, acc01);
            acc10 = fmaf(a1.w, b3.x, acc10);
            acc11 = fmaf(a1.w, b3.y, acc11);
        }
        const int row0 = ti * 32 + 2 * ty;
        const int col0 = tj * 32 + 2 * tx;
        *(float2*)&g_dot[(size_t)(row0 + 0) * n + col0] = make_float2(acc00, acc01);
        *(float2*)&g_dot[(size_t)(row0 + 1) * n + col0] = make_float2(acc10, acc11);

        if (ti == tj) {
            if (2 * ty     == 2 * tx    ) g_sq[row0]     = acc00;
            if (2 * ty     == 2 * tx + 1) g_sq[row0]     = acc01;
            if (2 * ty + 1 == 2 * tx    ) g_sq[row0 + 1] = acc10;
            if (2 * ty + 1 == 2 * tx + 1) g_sq[row0 + 1] = acc11;
        } else {
            float* Tr = Bs;                  // reuse: [32][33]
            __syncthreads();
            Tr[(2 * tx + 0) * 33 + 2 * ty + 0] = acc00;
            Tr[(2 * tx + 1) * 33 + 2 * ty + 0] = acc01;
            Tr[(2 * tx + 0) * 33 + 2 * ty + 1] = acc10;
            Tr[(2 * tx + 1) * 33 + 2 * ty + 1] = acc11;
            __syncthreads();
            int trow = tid >> 3;
            int tc4  = tid & 7;
            float4 mv;
            mv.x = Tr[trow * 33 + tc4 * 4 + 0];
            mv.y = Tr[trow * 33 + tc4 * 4 + 1];
            mv.z = Tr[trow * 33 + tc4 * 4 + 2];
            mv.w = Tr[trow * 33 + tc4 * 4 + 3];
            *(float4*)&g_dot[(size_t)(tj * 32 + trow) * n + ti * 32 + tc4 * 4] = mv;
        }
    } else {
        // labels: autodetect int64 vs int32 layout
        if (tid == 0) s_is64 = 1;
        __syncthreads();
        for (int idx = tid; idx < n / 2; idx += 256)
            if (lab32[2 * idx + 1] != 0) atomicExch(&s_is64, 0);
        __syncthreads();
        const bool is64 = (s_is64 != 0);
        for (int i2 = tid; i2 < n; i2 += 256)
            g_lab[i2] = is64 ? lab32[2 * i2] : lab32[i2];
    }
}

// ============================================================================
// Kernel B: grid = 640, one anchor per block.  Brute-force P-loop with exact
// 2.5-slot split (warps 0-3 hold 3 negative slots, warps 4-7 hold 2).
// Last-arriving block reduces all partials -> out[4] and resets the counter.
// ============================================================================
__global__ void __launch_bounds__(256)
triplet_kernel(float* __restrict__ out, int n) {
    __shared__ float pos_d[704];
    __shared__ int   sp, s_old;
    __shared__ float wsum[8];
    __shared__ int   wcnt[8];

    const int i    = blockIdx.x;          // anchor
    const int tid  = threadIdx.x;
    const int lane = tid & 31;
    const int wid  = tid >> 5;
    const unsigned lmask_lt = (1u << lane) - 1u;

    const int   li  = g_lab[i];
    const float sqi = g_sq[i];
    const float* __restrict__ drow = &g_dot[(size_t)i * n];

    float nk0 = BIGF, nk1 = BIGF, nk2 = BIGF;
    float pv0 = 0.f, pv1 = 0.f, pv2 = 0.f;
    bool  ip0 = false, ip1 = false, ip2 = false;
    {
        int j = tid;
        float dv = sqrtf(fmaxf(sqi + g_sq[j] - 2.0f * drow[j], 0.0f));
        bool same = (g_lab[j] == li);
        nk0 = same ? BIGF : dv;
        ip0 = same && (j != i);
        pv0 = dv + MARGIN;
    }
    {
        int j = tid + 256;
        float dv = sqrtf(fmaxf(sqi + g_sq[j] - 2.0f * drow[j], 0.0f));
        bool same = (g_lab[j] == li);
        nk1 = same ? BIGF : dv;
        ip1 = same && (j != i);
        pv1 = dv + MARGIN;
    }
    if (wid < 4) {                       // threads 0..127: j+512 in [512,640)
        int j = tid + 512;
        float dv = sqrtf(fmaxf(sqi + g_sq[j] - 2.0f * drow[j], 0.0f));
        bool same = (g_lab[j] == li);
        nk2 = same ? BIGF : dv;
        ip2 = same && (j != i);
        pv2 = dv + MARGIN;
    }

    if (tid == 0) sp = 0;
    __syncthreads();

    // warp-aggregated append of positives (d + MARGIN)
    {
        unsigned m = __ballot_sync(0xFFFFFFFFu, ip0);
        if (m) {
            int base = 0;
            if (lane == 0) base = atomicAdd(&sp, __popc(m));
            base = __shfl_sync(0xFFFFFFFFu, base, 0);
            if (ip0) pos_d[base + __popc(m & lmask_lt)] = pv0;
        }
    }
    {
        unsigned m = __ballot_sync(0xFFFFFFFFu, ip1);
        if (m) {
            int base = 0;
            if (lane == 0) base = atomicAdd(&sp, __popc(m));
            base = __shfl_sync(0xFFFFFFFFu, base, 0);
            if (ip1) pos_d[base + __popc(m & lmask_lt)] = pv1;
        }
    }
    if (wid < 4) {
        unsigned m = __ballot_sync(0xFFFFFFFFu, ip2);
        if (m) {
            int base = 0;
            if (lane == 0) base = atomicAdd(&sp, __popc(m));
            base = __shfl_sync(0xFFFFFFFFu, base, 0);
            if (ip2) pos_d[base + __popc(m & lmask_lt)] = pv2;
        }
    }
    __syncthreads();
    const int P = sp;
    if (tid < 4) pos_d[P + tid] = -BIGF;   // sentinel pad for 4-wide loop
    __syncthreads();

    // independent accumulator chains per j-slot; warps 4-7 run 2-slot loop
    float s0 = 0.f, s1 = 0.f, s2 = 0.f;
    int   c0 = 0,   c1 = 0,   c2 = 0;
    if (wid < 4) {
        for (int jj = 0; jj < P; jj += 4) {
            float4 tq = *(const float4*)&pos_d[jj];   // broadcast LDS.128
            if (nk0 < tq.x) { s0 += tq.x - nk0; c0++; }
            if (nk1 < tq.x) { s1 += tq.x - nk1; c1++; }
            if (nk2 < tq.x) { s2 += tq.x - nk2; c2++; }
            if (nk0 < tq.y) { s0 += tq.y - nk0; c0++; }
            if (nk1 < tq.y) { s1 += tq.y - nk1; c1++; }
            if (nk2 < tq.y) { s2 += tq.y - nk2; c2++; }
            if (nk0 < tq.z) { s0 += tq.z - nk0; c0++; }
            if (nk1 < tq.z) { s1 += tq.z - nk1; c1++; }
            if (nk2 < tq.z) { s2 += tq.z - nk2; c2++; }
            if (nk0 < tq.w) { s0 += tq.w - nk0; c0++; }
            if (nk1 < tq.w) { s1 += tq.w - nk1; c1++; }
            if (nk2 < tq.w) { s2 += tq.w - nk2; c2++; }
        }
    } else {
        for (int jj = 0; jj < P; jj += 4) {
            float4 tq = *(const float4*)&pos_d[jj];
            if (nk0 < tq.x) { s0 += tq.x - nk0; c0++; }
            if (nk1 < tq.x) { s1 += tq.x - nk1; c1++; }
            if (nk0 < tq.y) { s0 += tq.y - nk0; c0++; }
            if (nk1 < tq.y) { s1 += tq.y - nk1; c1++; }
            if (nk0 < tq.z) { s0 += tq.z - nk0; c0++; }
            if (nk1 < tq.z) { s1 += tq.z - nk1; c1++; }
            if (nk0 < tq.w) { s0 += tq.w - nk0; c0++; }
            if (nk1 < tq.w) { s1 += tq.w - nk1; c1++; }
        }
    }
    float lsum = s0 + s1 + s2;
    int   lcnt = c0 + c1 + c2;

    // block reduce
    #pragma unroll
    for (int off = 16; off; off >>= 1) {
        lsum += __shfl_down_sync(0xFFFFFFFFu, lsum, off);
        lcnt += __shfl_down_sync(0xFFFFFFFFu, lcnt, off);
    }
    if (lane == 0) { wsum[wid] = lsum; wcnt[wid] = lcnt; }
    __syncthreads();
    if (tid == 0) {
        float s = 0.f; int c = 0;
        #pragma unroll
        for (int w = 0; w < 8; w++) { s += wsum[w]; c += wcnt[w]; }
        g_bsum[i] = s;
        g_bcnt[i] = c;
        g_bval[i] = P * (n - 1 - P);
    }

    // -------- tail: last-arriving block finalizes --------
    __threadfence();
    __syncthreads();
    if (tid == 0) s_old = atomicAdd(&g_done, 1);
    __syncthreads();
    if (s_old == NANCH - 1) {
        float s = 0.f; int c = 0, v = 0;
        for (int idx = tid; idx < NANCH; idx += 256) {
            s += g_bsum[idx];
            c += g_bcnt[idx];
            v += g_bval[idx];
        }
        #pragma unroll
        for (int off = 16; off; off >>= 1) {
            s += __shfl_down_sync(0xFFFFFFFFu, s, off);
            c += __shfl_down_sync(0xFFFFFFFFu, c, off);
            v += __shfl_down_sync(0xFFFFFFFFu, v, off);
        }
        __shared__ float fs[8];
        __shared__ int   fc[8], fv[8];
        if (lane == 0) { fs[wid] = s; fc[wid] = c; fv[wid] = v; }
        __syncthreads();
        if (tid == 0) {
            float total = 0.f; int cnt = 0, val = 0;
            #pragma unroll
            for (int w = 0; w < 8; w++) { total += fs[w]; cnt += fc[w]; val += fv[w]; }
            float num_non   = (float)cnt;
            float num_valid = (float)val;
            out[0] = (cnt > 0) ? total / fmaxf(num_non, 1.0f) : 0.0f;
            out[1] = num_valid;
            out[2] = num_non;
            out[3] = num_non / (num_valid + 1e-16f);
            g_done = 0;                  // reset for next graph replay
            __threadfence();
        }
    }
}

extern "C" void kernel_launch(void* const* d_in, const int* in_sizes, int n_in,
                              void* d_out, int out_size) {
    const float* e   = (const float*)d_in[0];   // embeddings [8,80,128] fp32
    const int*   lab = (const int*)d_in[1];     // labels (int64 or int32 view)
    int n = in_sizes[1];                        // 640

    gemm_kernel<<<211, 256>>>(e, lab, n);
    triplet_kernel<<<NANCH, 256>>>((float*)d_out, n);
}

// round 17
// speedup vs baseline: 1.1354x; 1.1083x over previous
#include <cuda_runtime.h>

#define MARGIN  1.9f
#define NANCH   640
#define NMAXE   1024
#define BIGF    3.0e38f
#define BSCALE  8.0f             // 256 buckets over t in [0,32)

// Scratch (no allocation allowed)
__device__ float g_dot[640 * 640];   // full dot products (mirror filled from upper tiles)
__device__ float g_sq[NMAXE];        // = diag(dot), written by diagonal tiles
__device__ int   g_lab[NMAXE];
__device__ float g_bsum[NANCH];
__device__ int   g_bcnt[NANCH];
__device__ int   g_bval_[NANCH];
__device__ int   g_done = 0;         // kernel-B tail counter (reset by finalizer)

// ============================================================================
// Kernel A: grid = 211.  Blocks 0..209: upper-triangle 32x32 dot tiles
// (2x2 micro, full k=128; diag tiles emit g_sq; off-diag mirror via smem
// transpose).  Block 210: label normalization (int64/int32 autodetect).
// ============================================================================
__global__ void __launch_bounds__(256)
gemm_kernel(const float* __restrict__ e, const int* __restrict__ lab32, int n) {
    __shared__ float As[32 * 132];   // A tile rows x k (padded)
    __shared__ float Bs[128 * 32];   // B tile k-major (reused as transpose buf)
    __shared__ int   s_is64;

    const int b   = blockIdx.x;
    const int tid = threadIdx.x;
    const float4* e4 = (const float4*)e;   // 32 float4 per embedding row

    const int tiles_x    = n >> 5;                        // 20
    const int tri_blocks = (tiles_x * (tiles_x + 1)) / 2; // 210

    if (b < tri_blocks) {
        // invert triangular index -> (ti, tj), tj >= ti
        int ti = 0, rrem = b;
        #pragma unroll 1
        for (; ti < tiles_x; ti++) {
            int cnt = tiles_x - ti;
            if (rrem < cnt) break;
            rrem -= cnt;
        }
        const int tj = ti + rrem;

        const int tx = tid & 15;     // col pair (cols 2tx, 2tx+1)
        const int ty = tid >> 4;     // row pair (rows 2ty, 2ty+1)

        #pragma unroll
        for (int r = 0; r < 4; r++) {
            int lin = tid + r * 256;
            int row = lin >> 5;
            int c4  = lin & 31;
            float4 v = e4[(size_t)(ti * 32 + row) * 32 + c4];
            *(float4*)&As[row * 132 + c4 * 4] = v;
        }
        #pragma unroll
        for (int r = 0; r < 4; r++) {
            int lin = tid + r * 256;
            int j   = lin & 31;
            int c4  = lin >> 5;
            float4 v = e4[(size_t)(tj * 32 + j) * 32 + c4];
            Bs[(c4 * 4 + 0) * 32 + j] = v.x;
            Bs[(c4 * 4 + 1) * 32 + j] = v.y;
            Bs[(c4 * 4 + 2) * 32 + j] = v.z;
            Bs[(c4 * 4 + 3) * 32 + j] = v.w;
        }
        __syncthreads();

        float acc00 = 0.f, acc01 = 0.f, acc10 = 0.f, acc11 = 0.f;
        #pragma unroll 4
        for (int k4 = 0; k4 < 32; k4++) {
            float4 a0 = *(const float4*)&As[(2 * ty + 0) * 132 + 4 * k4];
            float4 a1 = *(const float4*)&As[(2 * ty + 1) * 132 + 4 * k4];
            float2 b0 = *(const float2*)&Bs[(4 * k4 + 0) * 32 + 2 * tx];
            float2 b1 = *(const float2*)&Bs[(4 * k4 + 1) * 32 + 2 * tx];
            float2 b2 = *(const float2*)&Bs[(4 * k4 + 2) * 32 + 2 * tx];
            float2 b3 = *(const float2*)&Bs[(4 * k4 + 3) * 32 + 2 * tx];
            acc00 = fmaf(a0.x, b0.x, acc00);
            acc01 = fmaf(a0.x, b0.y, acc01);
            acc10 = fmaf(a1.x, b0.x, acc10);
            acc11 = fmaf(a1.x, b0.y, acc11);
            acc00 = fmaf(a0.y, b1.x, acc00);
            acc01 = fmaf(a0.y, b1.y, acc01);
            acc10 = fmaf(a1.y, b1.x, acc10);
            acc11 = fmaf(a1.y, b1.y, acc11);
            acc00 = fmaf(a0.z, b2.x, acc00);
            acc01 = fmaf(a0.z, b2.y, acc01);
            acc10 = fmaf(a1.z, b2.x, acc10);
            acc11 = fmaf(a1.z, b2.y, acc11);
            acc00 = fmaf(a0.w, b3.x, acc00);
            acc01 = fmaf(a0.w, b3.y, acc01);
            acc10 = fmaf(a1.w, b3.x, acc10);
            acc11 = fmaf(a1.w, b3.y, acc11);
        }
        const int row0 = ti * 32 + 2 * ty;
        const int col0 = tj * 32 + 2 * tx;
        *(float2*)&g_dot[(size_t)(row0 + 0) * n + col0] = make_float2(acc00, acc01);
        *(float2*)&g_dot[(size_t)(row0 + 1) * n + col0] = make_float2(acc10, acc11);

        if (ti == tj) {
            if (2 * ty     == 2 * tx    ) g_sq[row0]     = acc00;
            if (2 * ty     == 2 * tx + 1) g_sq[row0]     = acc01;
            if (2 * ty + 1 == 2 * tx    ) g_sq[row0 + 1] = acc10;
            if (2 * ty + 1 == 2 * tx + 1) g_sq[row0 + 1] = acc11;
        } else {
            float* Tr = Bs;                  // reuse: [32][33]
            __syncthreads();
            Tr[(2 * tx + 0) * 33 + 2 * ty + 0] = acc00;
            Tr[(2 * tx + 1) * 33 + 2 * ty + 0] = acc01;
            Tr[(2 * tx + 0) * 33 + 2 * ty + 1] = acc10;
            Tr[(2 * tx + 1) * 33 + 2 * ty + 1] = acc11;
            __syncthreads();
            int trow = tid >> 3;
            int tc4  = tid & 7;
            float4 mv;
            mv.x = Tr[trow * 33 + tc4 * 4 + 0];
            mv.y = Tr[trow * 33 + tc4 * 4 + 1];
            mv.z = Tr[trow * 33 + tc4 * 4 + 2];
            mv.w = Tr[trow * 33 + tc4 * 4 + 3];
            *(float4*)&g_dot[(size_t)(tj * 32 + trow) * n + ti * 32 + tc4 * 4] = mv;
        }
    } else {
        // labels: autodetect int64 vs int32 layout
        if (tid == 0) s_is64 = 1;
        __syncthreads();
        for (int idx = tid; idx < n / 2; idx += 256)
            if (lab32[2 * idx + 1] != 0) atomicExch(&s_is64, 0);
        __syncthreads();
        const bool is64 = (s_is64 != 0);
        for (int i2 = tid; i2 < n; i2 += 256)
            g_lab[i2] = is64 ? lab32[2 * i2] : lab32[i2];
    }
}

// ============================================================================
// Kernel B: grid = 640, one anchor per block.  POSITIVE-side counting sort:
// histogram the ~64 positives' thresholds t = d_p + M into 256 buckets,
// prefix-scan counts and bucket sums; each of ~576 negatives then answers
// cnt/sum of {t_p > d_n} via O(1) suffix lookup + exact boundary-bucket scan.
// Last-arriving block reduces all partials -> out[4] and resets the counter.
// ============================================================================
__global__ void __launch_bounds__(256)
triplet_kernel(float* __restrict__ out, int n) {
    __shared__ int   hcnt[256];
    __shared__ int   pcs[257];       // exclusive prefix of counts; pcs[256]=P
    __shared__ int   cur[256];       // scatter cursors
    __shared__ float pvs[257];       // exclusive prefix of bucket sums; pvs[256]=tot
    __shared__ float bval[704];      // positives' t values grouped by bucket
    __shared__ int   swi[8], swi2[8];
    __shared__ float swf[8], swf2[8];
    __shared__ int   s_old;
    __shared__ float wsum[8];
    __shared__ int   wcnt[8];

    const int i    = blockIdx.x;          // anchor
    const int tid  = threadIdx.x;
    const int lane = tid & 31;
    const int wid  = tid >> 5;

    const int   li  = g_lab[i];
    const float sqi = g_sq[i];
    const float* __restrict__ drow = &g_dot[(size_t)i * n];

    hcnt[tid] = 0;
    __syncthreads();

    // classify j slots: negatives kept in regs (BIGF sentinel for same/self),
    // positives' thresholds t = d + M histogrammed. Exact 2.5-slot split.
    float nk0 = BIGF, nk1 = BIGF, nk2 = BIGF;
    float pv0 = 0.f, pv1 = 0.f, pv2 = 0.f;
    bool  ip0 = false, ip1 = false, ip2 = false;
    {
        int j = tid;
        float dv = sqrtf(fmaxf(sqi + g_sq[j] - 2.0f * drow[j], 0.0f));
        bool same = (g_lab[j] == li);
        nk0 = same ? BIGF : dv;
        ip0 = same && (j != i);
        pv0 = dv + MARGIN;
        if (ip0) atomicAdd(&hcnt[min(255, (int)(pv0 * BSCALE))], 1);
    }
    {
        int j = tid + 256;
        float dv = sqrtf(fmaxf(sqi + g_sq[j] - 2.0f * drow[j], 0.0f));
        bool same = (g_lab[j] == li);
        nk1 = same ? BIGF : dv;
        ip1 = same && (j != i);
        pv1 = dv + MARGIN;
        if (ip1) atomicAdd(&hcnt[min(255, (int)(pv1 * BSCALE))], 1);
    }
    if (wid < 4) {                       // threads 0..127: j+512 in [512,640)
        int j = tid + 512;
        float dv = sqrtf(fmaxf(sqi + g_sq[j] - 2.0f * drow[j], 0.0f));
        bool same = (g_lab[j] == li);
        nk2 = same ? BIGF : dv;
        ip2 = same && (j != i);
        pv2 = dv + MARGIN;
        if (ip2) atomicAdd(&hcnt[min(255, (int)(pv2 * BSCALE))], 1);
    }
    __syncthreads();

    // exclusive scan of counts -> pcs, cursors
    int vcnt = hcnt[tid];
    int inc = vcnt;
    #pragma unroll
    for (int off = 1; off < 32; off <<= 1) {
        int t = __shfl_up_sync(0xFFFFFFFFu, inc, off);
        if (lane >= off) inc += t;
    }
    if (lane == 31) swi[wid] = inc;
    __syncthreads();
    if (tid < 8) {
        int o = 0;
        for (int k = 0; k < tid; k++) o += swi[k];
        swi2[tid] = o;
    }
    __syncthreads();
    int exc = inc - vcnt + swi2[wid];
    pcs[tid] = exc;
    cur[tid] = exc;
    if (tid == 255) pcs[256] = exc + vcnt;
    __syncthreads();

    // scatter positives' thresholds grouped by bucket
    if (ip0) { int bb = min(255, (int)(pv0 * BSCALE)); bval[atomicAdd(&cur[bb], 1)] = pv0; }
    if (ip1) { int bb = min(255, (int)(pv1 * BSCALE)); bval[atomicAdd(&cur[bb], 1)] = pv1; }
    if (ip2) { int bb = min(255, (int)(pv2 * BSCALE)); bval[atomicAdd(&cur[bb], 1)] = pv2; }
    __syncthreads();

    // per-bucket sums -> exclusive scan pvs (pvs[256] = total sum)
    float sv = 0.f;
    {
        int s0 = pcs[tid], s1 = pcs[tid + 1];
        for (int k = s0; k < s1; k++) sv += bval[k];
    }
    float fin = sv;
    #pragma unroll
    for (int off = 1; off < 32; off <<= 1) {
        float t = __shfl_up_sync(0xFFFFFFFFu, fin, off);
        if (lane >= off) fin += t;
    }
    if (lane == 31) swf[wid] = fin;
    __syncthreads();
    if (tid < 8) {
        float o = 0.f;
        for (int k = 0; k < tid; k++) o += swf[k];
        swf2[tid] = o;
    }
    __syncthreads();
    pvs[tid] = fin - sv + swf2[wid];
    if (tid == 255) pvs[256] = fin + swf2[wid];
    __syncthreads();

    // negatives query: cnt/sum of thresholds t_p > d_n (strict).
    // BIGF sentinels yield exactly 0 contribution (bucket 255 empty, cl = P).
    const int   P    = pcs[256];
    const float tots = pvs[256];
    float lsum = 0.f;
    int   lcnt = 0;
    {
        int bb = min(255, (int)fminf(nk0 * BSCALE, 255.0f));
        int cl = pcs[bb];
        float sl = pvs[bb];
        int e1 = pcs[bb + 1];
        for (int k = pcs[bb]; k < e1; k++) {
            float v = bval[k];
            if (v <= nk0) { cl++; sl += v; }
        }
        int cg = P - cl;
        lcnt += cg;
        lsum += (tots - sl) - (float)cg * nk0;
    }
    {
        int bb = min(255, (int)fminf(nk1 * BSCALE, 255.0f));
        int cl = pcs[bb];
        float sl = pvs[bb];
        int e1 = pcs[bb + 1];
        for (int k = pcs[bb]; k < e1; k++) {
            float v = bval[k];
            if (v <= nk1) { cl++; sl += v; }
        }
        int cg = P - cl;
        lcnt += cg;
        lsum += (tots - sl) - (float)cg * nk1;
    }
    if (wid < 4) {
        int bb = min(255, (int)fminf(nk2 * BSCALE, 255.0f));
        int cl = pcs[bb];
        float sl = pvs[bb];
        int e1 = pcs[bb + 1];
        for (int k = pcs[bb]; k < e1; k++) {
            float v = bval[k];
            if (v <= nk2) { cl++; sl += v; }
        }
        int cg = P - cl;
        lcnt += cg;
        lsum += (tots - sl) - (float)cg * nk2;
    }

    // block reduce
    #pragma unroll
    for (int off = 16; off; off >>= 1) {
        lsum += __shfl_down_sync(0xFFFFFFFFu, lsum, off);
        lcnt += __shfl_down_sync(0xFFFFFFFFu, lcnt, off);
    }
    if (lane == 0) { wsum[wid] = lsum; wcnt[wid] = lcnt; }
    __syncthreads();
    if (tid == 0) {
        float s = 0.f; int c = 0;
        #pragma unroll
        for (int w = 0; w < 8; w++) { s += wsum[w]; c += wcnt[w]; }
        g_bsum[i]  = s;
        g_bcnt[i]  = c;
        g_bval_[i] = P * (n - 1 - P);
    }

    // -------- tail: last-arriving block finalizes --------
    __threadfence();
    __syncthreads();
    if (tid == 0) s_old = atomicAdd(&g_done, 1);
    __syncthreads();
    if (s_old == NANCH - 1) {
        float s = 0.f; int c = 0, v = 0;
        for (int idx = tid; idx < NANCH; idx += 256) {
            s += g_bsum[idx];
            c += g_bcnt[idx];
            v += g_bval_[idx];
        }
        #pragma unroll
        for (int off = 16; off; off >>= 1) {
            s += __shfl_down_sync(0xFFFFFFFFu, s, off);
            c += __shfl_down_sync(0xFFFFFFFFu, c, off);
            v += __shfl_down_sync(0xFFFFFFFFu, v, off);
        }
        __shared__ float fs[8];
        __shared__ int   fc[8], fv[8];
        if (lane == 0) { fs[wid] = s; fc[wid] = c; fv[wid] = v; }
        __syncthreads();
        if (tid == 0) {
            float total = 0.f; int cnt = 0, val = 0;
            #pragma unroll
            for (int w = 0; w < 8; w++) { total += fs[w]; cnt += fc[w]; val += fv[w]; }
            float num_non   = (float)cnt;
            float num_valid = (float)val;
            out[0] = (cnt > 0) ? total / fmaxf(num_non, 1.0f) : 0.0f;
            out[1] = num_valid;
            out[2] = num_non;
            out[3] = num_non / (num_valid + 1e-16f);
            g_done = 0;                  // reset for next graph replay
            __threadfence();
        }
    }
}

extern "C" void kernel_launch(void* const* d_in, const int* in_sizes, int n_in,
                              void* d_out, int out_size) {
    const float* e   = (const float*)d_in[0];   // embeddings [8,80,128] fp32
    const int*   lab = (const int*)d_in[1];     // labels (int64 or int32 view)
    int n = in_sizes[1];                        // 640

    gemm_kernel<<<211, 256>>>(e, lab, n);
    triplet_kernel<<<NANCH, 256>>>((float*)d_out, n);
}